// round 15
// baseline (speedup 1.0000x reference)
#include <cuda_runtime.h>
#include <stdint.h>
#include <math.h>

// CB:[B,L,3] f32, mask:[B,L] f32, Y:[B,M,3] f32, Yt:[B,M] i32, Ym:[B,M] i32
// out: Y_out[B,L,K,3] ++ Y_t_out[B,L,K] ++ Y_m_out[B,L,K] ++ D[B,L]  (all f32)

#define BB 8
#define LL 2048
#define MM 4096
#define KSEL 25
#define NT 256
#define NC 16            // candidates per thread
#define NWARP 8

typedef unsigned long long u64;
typedef unsigned int u32;

__device__ __forceinline__ u64 u64min(u64 a, u64 b) { return a < b ? a : b; }

__global__ __launch_bounds__(NT, 6)
void knn25_kernel(const float* __restrict__ CB,
                  const float* __restrict__ mask,
                  const float* __restrict__ Y,
                  const int*   __restrict__ Yt,
                  const int*   __restrict__ Ym,
                  float* __restrict__ out)
{
    // d2 bit patterns only (atom index reconstructed from slot): 16 KB
    __shared__ u32 sbits[NC * NT];
    // double-buffered per-warp minima (16B aligned for vectorized loads)
    __shared__ __align__(16) u64 wmin[2][NWARP];

    const int row  = blockIdx.x;          // b*LL + l
    const int b    = row >> 11;           // LL = 2048
    const int tid  = threadIdx.x;
    const int warp = tid >> 5;
    const int lane = tid & 31;

    const float* __restrict__ Yb  = Y  + (size_t)b * MM * 3;
    const int*   __restrict__ Ymb = Ym + b * MM;
    const int*   __restrict__ Ytb = Yt + b * MM;

    const size_t O1 = (size_t)BB * LL * KSEL * 3;
    const size_t O2 = O1 + (size_t)BB * LL * KSEL;
    const size_t O3 = O2 + (size_t)BB * LL * KSEL;

    // ---- Masked-row fast path (block-uniform; before any barrier) ----
    // mask==0 => all L2 = 1000 => top_k picks indices 0..24, D = sqrt(1000)
    if (mask[row] == 0.0f) {
        if (tid < KSEL) {
            const int m = tid;
            const size_t po = (size_t)row * KSEL + tid;
            out[po * 3 + 0] = Yb[m * 3 + 0];
            out[po * 3 + 1] = Yb[m * 3 + 1];
            out[po * 3 + 2] = Yb[m * 3 + 2];
            out[O1 + po]    = (float)Ytb[m];
            out[O2 + po]    = (float)Ymb[m];
            if (tid == 0) out[O3 + row] = sqrtf(1000.0f);
        }
        return;
    }

    const float cbx = CB[row * 3 + 0];
    const float cby = CB[row * 3 + 1];
    const float cbz = CB[row * 3 + 2];

    // ---- Phase 1: keys -> smem (u32 d2 bits); track 2 smallest + slots ----
    // key = (d2_bits << 32) | m, m = tid + i*256: monotone in d2, ties by m.
    // Real d2 bits <= ~0x469C4000 << 0xFFFFFFFF, so 0xFFFFFFFF marks consumed.
    u64 lk = ~0ull, ln = ~0ull;   // smallest, second smallest
    int lp = 0,    lnp = 0;       // their slots
    #pragma unroll
    for (int i = 0; i < NC; i++) {
        const int m = tid + (i << 8);
        const float yx = Yb[m * 3 + 0];
        const float yy = Yb[m * 3 + 1];
        const float yz = Yb[m * 3 + 2];
        const int   ym = Ymb[m];
        const float dx = cbx - yx, dy = cby - yy, dz = cbz - yz;
        const float d2 = fmaf(dx, dx, fmaf(dy, dy, dz * dz));
        const float d2e = (ym != 0) ? d2 : 1000.0f;
        const u32 bits = __float_as_uint(d2e);
        sbits[i * NT + tid] = bits;
        const u64 kk = ((u64)bits << 32) | (u32)m;
        if (kk < lk)      { ln = lk; lnp = lp; lk = kk; lp = i; }
        else if (kk < ln) { ln = kk; lnp = i; }
    }

    // initial per-warp minima -> wmin[0]
    {
        u64 w0 = lk;
        #pragma unroll
        for (int s = 16; s > 0; s >>= 1)
            w0 = u64min(w0, __shfl_xor_sync(0xffffffffu, w0, s));
        if (lane == 0) wmin[0][warp] = w0;
    }
    __syncthreads();

    // ---- Phase 2: 25 extraction rounds (R14 decision sequence, O(1) consume) ----
    u64 mykey = 0;
    #pragma unroll 1
    for (int r = 0; r < KSEL; r++) {
        const int cur = r & 1;

        // global min = min of 8 cached warp minima
        const ulonglong2* p2 = reinterpret_cast<const ulonglong2*>(wmin[cur]);
        const ulonglong2 v0 = p2[0], v1 = p2[1], v2 = p2[2], v3 = p2[3];
        const u64 g = u64min(u64min(u64min(v0.x, v0.y), u64min(v1.x, v1.y)),
                             u64min(u64min(v2.x, v2.y), u64min(v3.x, v3.y)));

        if (tid == r) mykey = g;           // thread r keeps the r-th smallest

        // unique owner consumes in O(1): mark slot, promote second smallest
        const bool iwin = (lk == g);
        if (iwin) {
            sbits[lp * NT + tid] = 0xFFFFFFFFu;   // consumed
            lk = ln;  lp = lnp;                   // reduce input ready now
        }

        // only the winning warp recomputes its minimum; others carry forward
        u64 nw;
        if (__ballot_sync(0xffffffffu, iwin)) {
            nw = lk;
            #pragma unroll
            for (int s = 16; s > 0; s >>= 1)
                nw = u64min(nw, __shfl_xor_sync(0xffffffffu, nw, s));
        } else {
            nw = wmin[cur][warp];
        }
        if (lane == 0) wmin[cur ^ 1][warp] = nw;

        // off-critical-path: winner refills its second-smallest from smem
        if (iwin) {
            u64 a1 = ~0ull, a2 = ~0ull; int q1 = 0, q2 = 0;
            #pragma unroll
            for (int i = 0; i < NC; i++) {
                const u32 bb = sbits[i * NT + tid];
                const u64 kk = ((u64)bb << 32) | (u32)(tid + (i << 8));
                if (kk < a1)      { a2 = a1; q2 = q1; a1 = kk; q1 = i; }
                else if (kk < a2) { a2 = kk; q2 = i; }
            }
            // a1 == lk at slot lp (unique keys); second smallest is a2
            ln = a2; lnp = q2;
        }
        __syncthreads();
    }

    // ---- Phase 3: gather + store (threads 0..24), R14-identical ----
    if (tid < KSEL) {
        const int   m  = (u32)mykey;
        const float d2 = __uint_as_float((u32)(mykey >> 32));

        const size_t po = (size_t)row * KSEL + tid;
        out[po * 3 + 0] = Yb[m * 3 + 0];
        out[po * 3 + 1] = Yb[m * 3 + 1];
        out[po * 3 + 2] = Yb[m * 3 + 2];
        out[O1 + po]    = (float)Ytb[m];
        out[O2 + po]    = (float)Ymb[m];
        if (tid == 0) out[O3 + row] = sqrtf(d2);
    }
}

extern "C" void kernel_launch(void* const* d_in, const int* in_sizes, int n_in,
                              void* d_out, int out_size)
{
    (void)in_sizes; (void)n_in; (void)out_size;
    const float* CB   = (const float*)d_in[0];
    const float* mask = (const float*)d_in[1];
    const float* Y    = (const float*)d_in[2];
    const int*   Yt   = (const int*)d_in[3];
    const int*   Ym   = (const int*)d_in[4];
    float* out = (float*)d_out;

    knn25_kernel<<<BB * LL, NT>>>(CB, mask, Y, Yt, Ym, out);
}

// round 16
// speedup vs baseline: 3.7288x; 3.7288x over previous
#include <cuda_runtime.h>
#include <stdint.h>
#include <math.h>

// CB:[B,L,3] f32, mask:[B,L] f32, Y:[B,M,3] f32, Yt:[B,M] i32, Ym:[B,M] i32
// out: Y_out[B,L,K,3] ++ Y_t_out[B,L,K] ++ Y_m_out[B,L,K] ++ D[B,L]  (all f32)

#define BB 8
#define LL 2048
#define MM 4096
#define KSEL 25
#define NT 256
#define NC 16            // candidates per thread, m = tid + i*256
#define NWARP 8
#define CAP 1024         // candidate buffer capacity

typedef unsigned long long u64;
typedef unsigned int u32;

// block-wide count of bits[] < T (strict). Uniform T, uniform control.
// Double-buffered via `par` (caller passes alternating parity starting at 1).
__device__ __forceinline__ int block_count(const u32* bits, u32 T,
                                           u32 (*wred)[NWARP], int& par,
                                           int warp, int lane)
{
    int c16 = 0;
    #pragma unroll
    for (int i = 0; i < NC; i++) c16 += (bits[i] < T) ? 1 : 0;
    u32 wc = __reduce_add_sync(0xffffffffu, (u32)c16);
    if (lane == 0) wred[par][warp] = wc;
    __syncthreads();
    int c = 0;
    #pragma unroll
    for (int w = 0; w < NWARP; w++) c += (int)wred[par][w];
    par ^= 1;
    return c;
}

__global__ __launch_bounds__(NT, 6)
void knn25_kernel(const float* __restrict__ CB,
                  const float* __restrict__ mask,
                  const float* __restrict__ Y,
                  const int*   __restrict__ Yt,
                  const int*   __restrict__ Ym,
                  float* __restrict__ out)
{
    __shared__ u64 cand[CAP];          // 8 KB
    __shared__ u64 res[KSEL];
    __shared__ u32 wred[2][NWARP];
    __shared__ int ncand;

    const int row  = blockIdx.x;       // b*LL + l
    const int b    = row >> 11;        // LL = 2048
    const int tid  = threadIdx.x;
    const int warp = tid >> 5;
    const int lane = tid & 31;

    const float* __restrict__ Yb  = Y  + (size_t)b * MM * 3;
    const int*   __restrict__ Ymb = Ym + b * MM;
    const int*   __restrict__ Ytb = Yt + b * MM;

    const size_t O1 = (size_t)BB * LL * KSEL * 3;
    const size_t O2 = O1 + (size_t)BB * LL * KSEL;
    const size_t O3 = O2 + (size_t)BB * LL * KSEL;

    // ---- Masked-row fast path (block-uniform, before any barrier) ----
    // mask==0 => all L2 = 1000 => top_k picks indices 0..24, D = sqrt(1000)
    if (mask[row] == 0.0f) {
        if (tid < KSEL) {
            const int m = tid;
            const size_t po = (size_t)row * KSEL + tid;
            out[po * 3 + 0] = Yb[m * 3 + 0];
            out[po * 3 + 1] = Yb[m * 3 + 1];
            out[po * 3 + 2] = Yb[m * 3 + 2];
            out[O1 + po]    = (float)Ytb[m];
            out[O2 + po]    = (float)Ymb[m];
            if (tid == 0) out[O3 + row] = sqrtf(1000.0f);
        }
        return;
    }

    const float cbx = CB[row * 3 + 0];
    const float cby = CB[row * 3 + 1];
    const float cbz = CB[row * 3 + 2];

    if (tid == 0) ncand = 0;

    // ---- Phase 1: d2 bit patterns in registers (R14-identical math) ----
    // ordering key = (d2_bits << 32) | m : monotone in d2, ties by smaller m
    u32 bits[NC];
    u32 lmin = 0xFFFFFFFFu;
    #pragma unroll
    for (int i = 0; i < NC; i++) {
        const int m = tid + (i << 8);
        const float yx = Yb[m * 3 + 0];
        const float yy = Yb[m * 3 + 1];
        const float yz = Yb[m * 3 + 2];
        const int   ym = Ymb[m];
        const float dx = cbx - yx, dy = cby - yy, dz = cbz - yz;
        const float d2 = fmaf(dx, dx, fmaf(dy, dy, dz * dz));
        const float d2e = (ym != 0) ? d2 : 1000.0f;
        bits[i] = __float_as_uint(d2e);
        lmin = umin(lmin, bits[i]);
    }

    // ---- Phase 2: block min of d2 bits (seed for threshold search) ----
    {
        u32 wm = __reduce_min_sync(0xffffffffu, lmin);
        if (lane == 0) wred[0][warp] = wm;
    }
    __syncthreads();
    u32 g = wred[0][0];
    #pragma unroll
    for (int w = 1; w < NWARP; w++) g = umin(g, wred[0][w]);

    // ---- Phase 3: find T with KSEL <= cnt(<T) <= CAP ----
    // geometric ascent from 4x min (float x4 == +2 exponent == +(2<<23) bits)
    int par = 1;                       // wred[0] just used by the min reduce
    u32 lo = g;                        // cnt(<g) == 0 < KSEL
    u32 T  = umin(g + (2u << 23), 0x7F800000u);
    int c;
    for (;;) {
        c = block_count(bits, T, wred, par, warp, lane);
        if (c >= KSEL) break;          // T = first bracket with enough mass
        lo = T;
        T  = umin(T + (2u << 23), 0x7F800000u);
    }
    u32 hi = T;
    int c_hi = c;
    bool tie = false;
    while (c_hi > CAP) {               // rare: shrink bracket by bit-bisection
        if (hi - lo <= 1u) { tie = true; break; }   // point mass at value `lo`
        u32 mid = lo + ((hi - lo) >> 1);
        c = block_count(bits, mid, wred, par, warp, lane);
        if (c < KSEL) lo = mid;
        else { hi = mid; c_hi = c; }
    }

    // ---- Phase 4: compact candidates into smem ----
    int Ctot;
    if (!tie) {
        #pragma unroll
        for (int i = 0; i < NC; i++) {
            if (bits[i] < hi) {
                int p = atomicAdd(&ncand, 1);
                cand[p] = ((u64)bits[i] << 32) | (u32)(tid + (i << 8));
            }
        }
        __syncthreads();
        Ctot = ncand;                  // == c_hi, in [KSEL, CAP]
    } else {
        // exact-tie fallback (degenerate inputs only): top-25 =
        // {bits < lo} ++ smallest-m elements with bits == lo, ascending m.
        #pragma unroll
        for (int i = 0; i < NC; i++) {
            if (bits[i] < lo) {
                int p = atomicAdd(&ncand, 1);
                cand[p] = ((u64)bits[i] << 32) | (u32)(tid + (i << 8));
            }
        }
        __syncthreads();
        const int c_lo = ncand;        // < KSEL
        const int rem  = KSEL - c_lo;
        int taken = 0, tpar = 0;
        // m = tid + i*256: ascending m == (i major, tid minor) order
        for (int i = 0; i < NC && taken < rem; i++) {
            const bool isT = (bits[i] == lo);
            const u32 wb = __ballot_sync(0xffffffffu, isT);
            if (lane == 0) wred[tpar][warp] = (u32)__popc(wb);
            __syncthreads();
            int pre = __popc(wb & ((1u << lane) - 1u));
            int tot = 0;
            #pragma unroll
            for (int w = 0; w < NWARP; w++) {
                const int v = (int)wred[tpar][w];
                if (w < warp) pre += v;
                tot += v;
            }
            if (isT && (taken + pre) < rem)
                cand[c_lo + taken + pre] =
                    ((u64)lo << 32) | (u32)(tid + (i << 8));
            taken += tot;
            tpar ^= 1;
        }
        __syncthreads();
        Ctot = KSEL;
    }

    // ---- Phase 5: exact rank-select (keys distinct: m embedded) ----
    // k-th smallest key has rank k-1; ranks of top-25 are exactly 0..24.
    for (int t = tid; t < Ctot; t += NT) {
        const u64 k = cand[t];
        int rk = 0;
        for (int j = 0; j < Ctot; j++) rk += (cand[j] < k) ? 1 : 0;
        if (rk < KSEL) res[rk] = k;
    }
    __syncthreads();

    // ---- Phase 6: gather + store (R14-identical) ----
    if (tid < KSEL) {
        const u64 kk = res[tid];
        const int   m  = (u32)kk;
        const float d2 = __uint_as_float((u32)(kk >> 32));

        const size_t po = (size_t)row * KSEL + tid;
        out[po * 3 + 0] = Yb[m * 3 + 0];
        out[po * 3 + 1] = Yb[m * 3 + 1];
        out[po * 3 + 2] = Yb[m * 3 + 2];
        out[O1 + po]    = (float)Ytb[m];
        out[O2 + po]    = (float)Ymb[m];
        if (tid == 0) out[O3 + row] = sqrtf(d2);
    }
}

extern "C" void kernel_launch(void* const* d_in, const int* in_sizes, int n_in,
                              void* d_out, int out_size)
{
    (void)in_sizes; (void)n_in; (void)out_size;
    const float* CB   = (const float*)d_in[0];
    const float* mask = (const float*)d_in[1];
    const float* Y    = (const float*)d_in[2];
    const int*   Yt   = (const int*)d_in[3];
    const int*   Ym   = (const int*)d_in[4];
    float* out = (float*)d_out;

    knn25_kernel<<<BB * LL, NT>>>(CB, mask, Y, Yt, Ym, out);
}